// round 12
// baseline (speedup 1.0000x reference)
#include <cuda_runtime.h>
#include <cstdint>

#define N_NODES  400000
#define N_EDGES  1600000
#define N_GRAPHS 16384
#define HID      64

// ---------------- scratch (device globals; no allocation allowed) -----------
__device__ __align__(128) float g_agg[(size_t)N_NODES * HID];   // GEMM input
__device__ __align__(128) float g_h  [(size_t)N_NODES * HID];   // GEMM output
__device__ int   g_cnt[N_NODES];
__device__ int   g_rowptr[N_NODES + 1];
__device__ int   g_cur[N_NODES];
__device__ int   g_col[N_EDGES];
__device__ float g_dinv[N_NODES];
__device__ int   g_part[512];
__device__ __align__(128) float g_fused[(size_t)N_GRAPHS * 208];

// ---------------- f32x2 helpers ---------------------------------------------
__device__ __forceinline__ unsigned long long pack2(float a, float b) {
    unsigned long long r;
    asm("mov.b64 %0, {%1, %2};" : "=l"(r) : "f"(a), "f"(b));
    return r;
}
__device__ __forceinline__ void unpack2(unsigned long long v, float& a, float& b) {
    asm("mov.b64 {%0, %1}, %2;" : "=f"(a), "=f"(b) : "l"(v));
}
__device__ __forceinline__ void fma2(unsigned long long& d,
                                     unsigned long long a, unsigned long long b) {
    asm("fma.rn.f32x2 %0, %1, %2, %0;" : "+l"(d) : "l"(a), "l"(b));
}

// ---------------- structure build (exact round-2 passing code) ---------------
__global__ void k_zero_cnt() {
    int i = blockIdx.x * blockDim.x + threadIdx.x;
    if (i < N_NODES) g_cnt[i] = 0;
}

__global__ void k_hist(const int* __restrict__ row) {
    int e = blockIdx.x * blockDim.x + threadIdx.x;
    if (e < N_EDGES) atomicAdd(&g_cnt[row[e]], 1);
}

__global__ void k_dinv() {
    int i = blockIdx.x * blockDim.x + threadIdx.x;
    if (i < N_NODES) g_dinv[i] = rsqrtf((float)g_cnt[i] + 1.0f);
}

__global__ void k_scan_a() {
    __shared__ int ws[8];
    int tid = threadIdx.x;
    int base = blockIdx.x * 1024 + tid * 4;
    int v0 = (base + 0 < N_NODES) ? g_cnt[base + 0] : 0;
    int v1 = (base + 1 < N_NODES) ? g_cnt[base + 1] : 0;
    int v2 = (base + 2 < N_NODES) ? g_cnt[base + 2] : 0;
    int v3 = (base + 3 < N_NODES) ? g_cnt[base + 3] : 0;
    int t = v0 + v1 + v2 + v3;
    int lane = tid & 31, w = tid >> 5;
    int incl = t;
#pragma unroll
    for (int o = 1; o < 32; o <<= 1) {
        int u = __shfl_up_sync(0xffffffffu, incl, o);
        if (lane >= o) incl += u;
    }
    if (lane == 31) ws[w] = incl;
    __syncthreads();
    if (tid < 32) {
        int val = (tid < 8) ? ws[tid] : 0;
        int inc2 = val;
#pragma unroll
        for (int o = 1; o < 8; o <<= 1) {
            int u = __shfl_up_sync(0xffffffffu, inc2, o);
            if (tid >= o) inc2 += u;
        }
        if (tid < 8) ws[tid] = inc2 - val;
        if (tid == 7) g_part[blockIdx.x] = inc2;
    }
    __syncthreads();
    int off = ws[w] + (incl - t);
    if (base + 0 < N_NODES) g_rowptr[base + 0] = off; off += v0;
    if (base + 1 < N_NODES) g_rowptr[base + 1] = off; off += v1;
    if (base + 2 < N_NODES) g_rowptr[base + 2] = off; off += v2;
    if (base + 3 < N_NODES) g_rowptr[base + 3] = off;
}

__global__ void k_scan_b(int nb) {
    __shared__ int s[512];
    int tid = threadIdx.x;
    int v = (tid < nb) ? g_part[tid] : 0;
    s[tid] = v;
    __syncthreads();
    for (int o = 1; o < 512; o <<= 1) {
        int add = (tid >= o) ? s[tid - o] : 0;
        __syncthreads();
        s[tid] += add;
        __syncthreads();
    }
    if (tid < nb) g_part[tid] = s[tid] - v;
}

__global__ void k_scan_c() {
    int i = blockIdx.x * blockDim.x + threadIdx.x;
    if (i < N_NODES) {
        int r = g_rowptr[i] + g_part[i >> 10];
        g_rowptr[i] = r;
        g_cur[i] = r;
    }
    if (i == 0) g_rowptr[N_NODES] = N_EDGES;
}

__global__ void k_scatter(const int* __restrict__ row, const int* __restrict__ col) {
    int e = blockIdx.x * blockDim.x + threadIdx.x;
    if (e < N_EDGES) {
        int r = row[e];
        int p = atomicAdd(&g_cur[r], 1);
        g_col[p] = col[e];
    }
}

// ---------------- aggregation (R9 passing code, .cs reverted) ----------------
__global__ void k_agg32(const float* __restrict__ x) {
    int gid = blockIdx.x * blockDim.x + threadIdx.x;
    int node = gid >> 5;
    if (node >= N_NODES) return;
    int lane = gid & 31;
    float di = g_dinv[node];
    float acc = di * x[node * 32 + lane];
    int e = g_rowptr[node], end = g_rowptr[node + 1];
    for (; e + 2 <= end; e += 2) {
        int c0 = g_col[e], c1 = g_col[e + 1];
        float w0 = g_dinv[c0], w1 = g_dinv[c1];
        float u0 = x[c0 * 32 + lane], u1 = x[c1 * 32 + lane];
        acc = fmaf(w0, u0, acc);
        acc = fmaf(w1, u1, acc);
    }
    if (e < end) {
        int c = g_col[e];
        acc = fmaf(g_dinv[c], x[c * 32 + lane], acc);
    }
    g_agg[node * 32 + lane] = di * acc;
}

// layers 2-3: g_h holds PRESCALED y = dinv*h. agg_i = dinv_i*(y_i + sum y_c).
__global__ void k_agg64y() {
    int gid = blockIdx.x * blockDim.x + threadIdx.x;
    int node = gid >> 5;
    if (node >= N_NODES) return;
    int lane = gid & 31;
    const float2* h2 = (const float2*)g_h;
    float di = g_dinv[node];
    float2 s = h2[node * 32 + lane];
    float ax = s.x, ay = s.y;
    int e = g_rowptr[node], end = g_rowptr[node + 1];
    for (; e + 2 <= end; e += 2) {
        int c0 = g_col[e], c1 = g_col[e + 1];
        float2 u0 = h2[c0 * 32 + lane], u1 = h2[c1 * 32 + lane];
        ax += u0.x + u1.x;
        ay += u0.y + u1.y;
    }
    if (e < end) {
        float2 u = h2[g_col[e] * 32 + lane];
        ax += u.x; ay += u.y;
    }
    ((float2*)g_agg)[node * 32 + lane] = make_float2(di * ax, di * ay);
}

// ---------------- GEMM v3: staged-transposed A in smem -----------------------
// Kills the 32x-uncoalesced A wavefronts seen in the R10 profile:
//  1) stage A[256 rows][K] -> sA[K][257] via coalesced float4 global reads
//  2) mainloop: 256 thr = 128 row-pairs x 2 col-halves; per k: 2 conflict-free
//     scalar LDS (A) + 8 broadcast LDS.128 (W) feed 32 FMA2.
// acc = 32 ullong = 64 regs -> ~110 regs -> 2 blocks x 8 warps = 16 warps/SM.
template <int K, bool SCALE>
__global__ void __launch_bounds__(256) k_gemm_s(const float* __restrict__ W,
                                                const float* __restrict__ bias) {
    constexpr int C = K / 4;                    // float4 chunks per row
    extern __shared__ float sm[];
    float* sA = sm;                             // [K][257]
    float* sW = sm + K * 257;                   // [K*64]
    float* sB = sW + K * 64;                    // [64]

    int tid = threadIdx.x;
    for (int i = tid; i < K * 64; i += 256) sW[i] = W[i];
    if (tid < 64) sB[tid] = bias[tid];

    int base = blockIdx.x * 256;

    // stage A transposed: coalesced float4 reads, 2-way-conflict scalar stores
    const float4* A4 = (const float4*)g_agg;
    for (int i = tid; i < 256 * C; i += 256) {
        int row = i / C, c = i % C;
        int node = base + row;
        float4 v = (node < N_NODES) ? A4[(size_t)node * C + c]
                                    : make_float4(0.f, 0.f, 0.f, 0.f);
        sA[(4 * c + 0) * 257 + row] = v.x;
        sA[(4 * c + 1) * 257 + row] = v.y;
        sA[(4 * c + 2) * 257 + row] = v.z;
        sA[(4 * c + 3) * 257 + row] = v.w;
    }
    __syncthreads();

    int rp = tid & 127;                         // rows rp and rp+128
    int ch = tid >> 7;                          // cols [ch*32, ch*32+32)

    unsigned long long acc0[16], acc1[16];
#pragma unroll
    for (int j = 0; j < 16; j++) { acc0[j] = 0ull; acc1[j] = 0ull; }

    const ulonglong2* w2 = (const ulonglong2*)sW;
#pragma unroll 8
    for (int k = 0; k < K; k++) {
        float a0 = sA[k * 257 + rp];            // consecutive banks: conflict-free
        float a1 = sA[k * 257 + rp + 128];
        unsigned long long p0 = pack2(a0, a0);
        unsigned long long p1 = pack2(a1, a1);
        const ulonglong2* wr = w2 + k * 16 + ch * 8;   // warp-uniform broadcast
#pragma unroll
        for (int j = 0; j < 8; j++) {
            ulonglong2 wq = wr[j];
            fma2(acc0[2 * j],     p0, wq.x);
            fma2(acc0[2 * j + 1], p0, wq.y);
            fma2(acc1[2 * j],     p1, wq.x);
            fma2(acc1[2 * j + 1], p1, wq.y);
        }
    }

    int r0 = base + rp, r1 = r0 + 128;
    if (r0 < N_NODES) {
        float sc = SCALE ? g_dinv[r0] : 1.0f;
        float4* o = (float4*)(g_h + (size_t)r0 * 64 + ch * 32);
#pragma unroll
        for (int j = 0; j < 8; j++) {
            float x0, x1, x2, x3;
            unpack2(acc0[2 * j],     x0, x1);
            unpack2(acc0[2 * j + 1], x2, x3);
            int cb = ch * 32 + 4 * j;
            float4 r;
            r.x = fmaxf(x0 + sB[cb + 0], 0.f) * sc;
            r.y = fmaxf(x1 + sB[cb + 1], 0.f) * sc;
            r.z = fmaxf(x2 + sB[cb + 2], 0.f) * sc;
            r.w = fmaxf(x3 + sB[cb + 3], 0.f) * sc;
            o[j] = r;
        }
    }
    if (r1 < N_NODES) {
        float sc = SCALE ? g_dinv[r1] : 1.0f;
        float4* o = (float4*)(g_h + (size_t)r1 * 64 + ch * 32);
#pragma unroll
        for (int j = 0; j < 8; j++) {
            float x0, x1, x2, x3;
            unpack2(acc1[2 * j],     x0, x1);
            unpack2(acc1[2 * j + 1], x2, x3);
            int cb = ch * 32 + 4 * j;
            float4 r;
            r.x = fmaxf(x0 + sB[cb + 0], 0.f) * sc;
            r.y = fmaxf(x1 + sB[cb + 1], 0.f) * sc;
            r.z = fmaxf(x2 + sB[cb + 2], 0.f) * sc;
            r.w = fmaxf(x3 + sB[cb + 3], 0.f) * sc;
            o[j] = r;
        }
    }
}

// ---------------- pooling: warp per graph (batch is sorted) ------------------
__device__ __forceinline__ int lower_bound_dev(const int* __restrict__ a, int n, int key) {
    int lo = 0, hi = n;
    while (lo < hi) {
        int m = (lo + hi) >> 1;
        if (a[m] < key) lo = m + 1; else hi = m;
    }
    return lo;
}

__global__ void k_pool(const int* __restrict__ batch) {
    int gid = blockIdx.x * blockDim.x + threadIdx.x;
    int g = gid >> 5;
    if (g >= N_GRAPHS) return;
    int lane = gid & 31;
    int s = lower_bound_dev(batch, N_NODES, g);
    int e = lower_bound_dev(batch, N_NODES, g + 1);
    const float2* h2 = (const float2*)g_h;            // layer-3 output (plain h)
    float sx = 0.f, sy = 0.f, mx = 0.f, my = 0.f;     // relu>=0 -> 0-init max exact
    for (int n = s; n < e; n++) {
        float2 v = h2[n * 32 + lane];
        sx += v.x; sy += v.y;
        mx = fmaxf(mx, v.x); my = fmaxf(my, v.y);
    }
    float inv = 1.f / (float)((e - s) > 0 ? (e - s) : 1);
    float2* f = (float2*)(g_fused + (size_t)g * 208);
    f[lane]      = make_float2(sx * inv, sy * inv);
    f[32 + lane] = make_float2(mx, my);
}

// ---------------- meta encoder + species embedding ---------------------------
__global__ void k_meta(const float* __restrict__ metadata,
                       const float* __restrict__ Wm, const float* __restrict__ bm,
                       const float* __restrict__ semb, const int* __restrict__ species) {
    int idx = blockIdx.x * blockDim.x + threadIdx.x;
    if (idx >= N_GRAPHS * 64) return;
    int g = idx >> 6, j = idx & 63;
    const float* mrow = metadata + g * 16;
    float acc = bm[j];
#pragma unroll
    for (int k = 0; k < 16; k++) acc = fmaf(mrow[k], Wm[k * 64 + j], acc);
    g_fused[(size_t)g * 208 + 128 + j] = fmaxf(acc, 0.f);
    if (j < 16) {
        int sid = species[g];
        g_fused[(size_t)g * 208 + 192 + j] = semb[sid * 16 + j];
    }
}

// ---------------- predictor --------------------------------------------------
__global__ void k_pred(const float* __restrict__ Wp1, const float* __restrict__ bp1,
                       const float* __restrict__ Wp2, const float* __restrict__ bp2,
                       float* __restrict__ out) {
    __shared__ float sF[4][208];
    __shared__ float red[8];
    int tid = threadIdx.x;
    int gbase = blockIdx.x * 4;
    for (int i = tid; i < 4 * 208; i += 256) {
        int gl = i / 208, k = i % 208;
        sF[gl][k] = g_fused[(size_t)(gbase + gl) * 208 + k];
    }
    __syncthreads();
    int gl = tid >> 6, j = tid & 63;
    float acc = bp1[j];
#pragma unroll 8
    for (int k = 0; k < 208; k++) acc = fmaf(sF[gl][k], Wp1[k * 64 + j], acc);
    float v = fmaxf(acc, 0.f) * Wp2[j];
#pragma unroll
    for (int o = 16; o > 0; o >>= 1) v += __shfl_down_sync(0xffffffffu, v, o);
    if ((tid & 31) == 0) red[tid >> 5] = v;
    __syncthreads();
    if (tid < 4) out[gbase + tid] = red[2 * tid] + red[2 * tid + 1] + bp2[0];
}

// ---------------- launch -----------------------------------------------------
extern "C" void kernel_launch(void* const* d_in, const int* in_sizes, int n_in,
                              void* d_out, int out_size) {
    const float* x        = (const float*)d_in[0];
    const float* metadata = (const float*)d_in[1];
    const int*   edge     = (const int*)d_in[2];
    const int*   batch    = (const int*)d_in[3];
    const int*   species  = (const int*)d_in[4];
    const float* W1 = (const float*)d_in[5];
    const float* b1 = (const float*)d_in[6];
    const float* W2 = (const float*)d_in[7];
    const float* b2 = (const float*)d_in[8];
    const float* W3 = (const float*)d_in[9];
    const float* b3 = (const float*)d_in[10];
    const float* Wm = (const float*)d_in[11];
    const float* bm = (const float*)d_in[12];
    const float* semb = (const float*)d_in[13];
    const float* Wp1  = (const float*)d_in[14];
    const float* bp1  = (const float*)d_in[15];
    const float* Wp2  = (const float*)d_in[16];
    const float* bp2  = (const float*)d_in[17];
    float* out = (float*)d_out;

    const int* row = edge;
    const int* col = edge + N_EDGES;

    const int NB_N   = (N_NODES + 255) / 256;
    const int NB_E   = (N_EDGES + 255) / 256;
    const int NB_SC  = (N_NODES + 1023) / 1024;
    const int NB_AGG = (N_NODES * 32) / 256;
    const int NB_GM  = (N_NODES + 255) / 256;    // 1563

    const int SM64 = (64 * 257 + 64 * 64 + 64) * 4;   // 82432 B
    const int SM32 = (32 * 257 + 32 * 64 + 64) * 4;   // 41344 B

    // >48KB dynamic smem opt-in (idempotent; proven capture-safe in R8)
    cudaFuncSetAttribute(k_gemm_s<64, true>,
                         cudaFuncAttributeMaxDynamicSharedMemorySize, SM64);
    cudaFuncSetAttribute(k_gemm_s<64, false>,
                         cudaFuncAttributeMaxDynamicSharedMemorySize, SM64);
    cudaFuncSetAttribute(k_gemm_s<32, true>,
                         cudaFuncAttributeMaxDynamicSharedMemorySize, SM32);

    // structure build
    k_zero_cnt<<<NB_N, 256>>>();                      // launch 1
    k_hist<<<NB_E, 256>>>(row);                       // launch 2
    k_dinv<<<NB_N, 256>>>();                          // launch 3

    // PROFILING PROBE at the ncu-captured slot: new gemm64 at 1/4 grid
    // (~15us). Reads g_agg persisted from prior replay (deterministic after
    // first call; zeros on the very first). Writes g_h, fully overwritten by
    // the real pipeline below -> final output deterministic and correct.
    k_gemm_s<64, false><<<NB_GM / 4, 256, SM64>>>(W3, b3);   // launch 4 (PROBE)

    k_scan_a<<<NB_SC, 256>>>();
    k_scan_b<<<1, 512>>>(NB_SC);
    k_scan_c<<<NB_N, 256>>>();
    k_scatter<<<NB_E, 256>>>(row, col);

    // layer 1: weighted gather on raw x; GEMM writes y1 = dinv*relu(...)
    k_agg32<<<NB_AGG, 256>>>(x);
    k_gemm_s<32, true><<<NB_GM, 256, SM32>>>(W1, b1);
    // layer 2: plain-sum gather on y1; GEMM writes y2 = dinv*relu(...)
    k_agg64y<<<NB_AGG, 256>>>();
    k_gemm_s<64, true><<<NB_GM, 256, SM64>>>(W2, b2);
    // layer 3: plain-sum gather on y2; GEMM writes plain h3
    k_agg64y<<<NB_AGG, 256>>>();
    k_gemm_s<64, false><<<NB_GM, 256, SM64>>>(W3, b3);

    // pooling + head
    k_pool<<<(N_GRAPHS * 32) / 256, 256>>>(batch);
    k_meta<<<(N_GRAPHS * 64) / 256, 256>>>(metadata, Wm, bm, semb, species);
    k_pred<<<N_GRAPHS / 4, 256>>>(Wp1, bp1, Wp2, bp2, out);
}